// round 2
// baseline (speedup 1.0000x reference)
#include <cuda_runtime.h>
#include <math.h>
#include <stdint.h>

// ---------------------------------------------------------------------------
// Problem constants
// ---------------------------------------------------------------------------
#define BATCH    256
#define RESOL    14
#define NTOK     196
#define NQTOK    49
#define INDIM    384
#define HEADS    12
#define KD       16
#define VD       32
#define KVD      576
#define KEYATTN  192
#define VALATTN  384
#define OUTDIM   512
#define ATTNSCALE 0.25f
#define BN_EPS   1e-5f

#define M1 (BATCH*NTOK)   // 50176
#define M2 (BATCH*NQTOK)  // 12544

// Scratch (device globals)
__device__ float g_kv[(size_t)M1 * KVD];
__device__ float g_q [(size_t)M2 * KEYATTN];
__device__ float g_ao[(size_t)M2 * VALATTN];
__device__ float g_btab[(size_t)HEADS * NQTOK * NTOK];   // precomputed bias

// ---------------------------------------------------------------------------
// tf32 helpers
// ---------------------------------------------------------------------------
__device__ __forceinline__ uint32_t f2tf32(float f) {
    uint32_t u;
    asm("cvt.rna.tf32.f32 %0, %1;" : "=r"(u) : "f"(f));
    return u;
}

__device__ __forceinline__ void mma_tf32(float* c, const uint32_t* a, const uint32_t* b) {
    asm volatile(
        "mma.sync.aligned.m16n8k8.row.col.f32.tf32.tf32.f32 "
        "{%0,%1,%2,%3}, {%4,%5,%6,%7}, {%8,%9}, {%0,%1,%2,%3};\n"
        : "+f"(c[0]), "+f"(c[1]), "+f"(c[2]), "+f"(c[3])
        : "r"(a[0]), "r"(a[1]), "r"(a[2]), "r"(a[3]), "r"(b[0]), "r"(b[1]));
}

// ---------------------------------------------------------------------------
// tf32 tensor-core GEMM + BatchNorm epilogue.
// C[m,n] = (sum_k A[m,k]*W[n,k]) * sc[n] + bi[n]
// Tile: BM=128, BN=64, BK=32. 256 threads = 8 warps (4 m x 2 n), warp 32x32.
// Smem layouts k-major with pad 5 for (near) conflict-free 32-bit LDS.
// ---------------------------------------------------------------------------
template<bool GATHER>
__global__ __launch_bounds__(256)
void gemm_tf32_bn(const float* __restrict__ A, const float* __restrict__ W,
                  const float* __restrict__ bn_g, const float* __restrict__ bn_b,
                  const float* __restrict__ bn_m, const float* __restrict__ bn_v,
                  float* __restrict__ C, int N)
{
    __shared__ uint32_t As[32][133];   // [k][m]
    __shared__ uint32_t Bs[32][69];    // [k][n]

    const int tid  = threadIdx.x;
    const int bm   = blockIdx.y * 128;
    const int bn   = blockIdx.x * 64;
    const int warp = tid >> 5;
    const int lane = tid & 31;
    const int wm   = (warp >> 1) * 32;
    const int wn   = (warp & 1) * 32;
    const int g8   = lane >> 2;
    const int tg   = lane & 3;

    // Global-load mapping: row = lrow + r*32, col chunk lcol (float4)
    const int lrow = tid >> 3;        // 0..31
    const int lcol = (tid & 7) * 4;   // 0,4,...,28

    int asrc[4];
#pragma unroll
    for (int r = 0; r < 4; r++) {
        int m = bm + lrow + r * 32;
        if (GATHER) {
            int b  = m / NQTOK;
            int qq = m - b * NQTOK;
            int qi = qq / 7;
            int qj = qq - qi * 7;
            asrc[r] = b * NTOK + qi * 2 * RESOL + qj * 2;
        } else {
            asrc[r] = m;
        }
    }
    int bsrc[2];
#pragma unroll
    for (int r = 0; r < 2; r++) bsrc[r] = bn + lrow + r * 32;

    float4 ar[4], br[2];

    auto gload = [&](int k0) {
#pragma unroll
        for (int r = 0; r < 4; r++)
            ar[r] = *(const float4*)(A + (size_t)asrc[r] * INDIM + k0 + lcol);
#pragma unroll
        for (int r = 0; r < 2; r++)
            br[r] = *(const float4*)(W + (size_t)bsrc[r] * INDIM + k0 + lcol);
    };
    auto stage = [&]() {
#pragma unroll
        for (int r = 0; r < 4; r++) {
            int row = lrow + r * 32;
            As[lcol + 0][row] = f2tf32(ar[r].x);
            As[lcol + 1][row] = f2tf32(ar[r].y);
            As[lcol + 2][row] = f2tf32(ar[r].z);
            As[lcol + 3][row] = f2tf32(ar[r].w);
        }
#pragma unroll
        for (int r = 0; r < 2; r++) {
            int row = lrow + r * 32;
            Bs[lcol + 0][row] = f2tf32(br[r].x);
            Bs[lcol + 1][row] = f2tf32(br[r].y);
            Bs[lcol + 2][row] = f2tf32(br[r].z);
            Bs[lcol + 3][row] = f2tf32(br[r].w);
        }
    };

    float acc[2][4][4] = {};

    gload(0);
    stage();
    __syncthreads();

    const int NIT = INDIM / 32;   // 12
    for (int it = 0; it < NIT; it++) {
        if (it + 1 < NIT) gload((it + 1) * 32);

#pragma unroll
        for (int ks = 0; ks < 4; ks++) {
            const int kb = ks * 8;
            uint32_t af[2][4];
#pragma unroll
            for (int mi = 0; mi < 2; mi++) {
                int m0 = wm + mi * 16 + g8;
                af[mi][0] = As[kb + tg    ][m0];
                af[mi][1] = As[kb + tg    ][m0 + 8];
                af[mi][2] = As[kb + tg + 4][m0];
                af[mi][3] = As[kb + tg + 4][m0 + 8];
            }
            uint32_t bf[4][2];
#pragma unroll
            for (int ni = 0; ni < 4; ni++) {
                int n0 = wn + ni * 8 + g8;
                bf[ni][0] = Bs[kb + tg    ][n0];
                bf[ni][1] = Bs[kb + tg + 4][n0];
            }
#pragma unroll
            for (int mi = 0; mi < 2; mi++)
#pragma unroll
                for (int ni = 0; ni < 4; ni++)
                    mma_tf32(acc[mi][ni], af[mi], bf[ni]);
        }
        __syncthreads();
        if (it + 1 < NIT) {
            stage();
            __syncthreads();
        }
    }

    // BN epilogue: c0,c1 at row g8 cols 2tg,2tg+1 ; c2,c3 at row g8+8
#pragma unroll
    for (int ni = 0; ni < 4; ni++) {
        int n0 = bn + wn + ni * 8 + 2 * tg;
        float sc0 = bn_g[n0] * rsqrtf(bn_v[n0] + BN_EPS);
        float bi0 = bn_b[n0] - bn_m[n0] * sc0;
        float sc1 = bn_g[n0 + 1] * rsqrtf(bn_v[n0 + 1] + BN_EPS);
        float bi1 = bn_b[n0 + 1] - bn_m[n0 + 1] * sc1;
#pragma unroll
        for (int mi = 0; mi < 2; mi++) {
#pragma unroll
            for (int rr = 0; rr < 2; rr++) {
                int mrow = bm + wm + mi * 16 + g8 + rr * 8;
                float2 val;
                val.x = fmaf(acc[mi][ni][rr * 2 + 0], sc0, bi0);
                val.y = fmaf(acc[mi][ni][rr * 2 + 1], sc1, bi1);
                *(float2*)(C + (size_t)mrow * N + n0) = val;
            }
        }
    }
}

// ---------------------------------------------------------------------------
// Precompute bias table: btab[h][q][n] = biases[h, bias_idxs[q,n]]
// ---------------------------------------------------------------------------
__global__ __launch_bounds__(256)
void bias_pre_kernel(const float* __restrict__ biases, const int* __restrict__ idxs,
                     float* __restrict__ tab)
{
    int i = blockIdx.x * 256 + threadIdx.x;
    if (i < NQTOK * NTOK) {
        int id = idxs[i];
#pragma unroll
        for (int h = 0; h < HEADS; h++)
            tab[(size_t)h * (NQTOK * NTOK) + i] = biases[h * NTOK + id];
    }
}

// ---------------------------------------------------------------------------
// Attention: one block per (b, h). 256 threads = 8 warps.
// ---------------------------------------------------------------------------
__global__ __launch_bounds__(256)
void attn_kernel(const float* __restrict__ kv, const float* __restrict__ q,
                 const float* __restrict__ btab, float* __restrict__ ao)
{
    __shared__ float qs[NQTOK * KD];
    __shared__ float ks[NTOK * KD];
    __shared__ float vs[NTOK * VD];
    __shared__ float pbuf[8 * NTOK];

    const int tid = threadIdx.x;
    const int b = blockIdx.x / HEADS;
    const int h = blockIdx.x - b * HEADS;
    const float* bt = btab + (size_t)h * (NQTOK * NTOK);

    for (int i = tid; i < NQTOK * KD; i += 256) {
        int qi = i / KD, d = i - qi * KD;
        qs[i] = q[(size_t)(b * NQTOK + qi) * KEYATTN + h * KD + d];
    }
    for (int i = tid; i < NTOK * KD; i += 256) {
        int n = i / KD, d = i - n * KD;
        ks[i] = kv[(size_t)(b * NTOK + n) * KVD + h * (KD + VD) + d];
    }
    for (int i = tid; i < NTOK * VD; i += 256) {
        int n = i / VD, d = i - n * VD;
        vs[i] = kv[(size_t)(b * NTOK + n) * KVD + h * (KD + VD) + KD + d];
    }
    __syncthreads();

    const int w = tid >> 5;
    const int l = tid & 31;

    for (int qq = w; qq < NQTOK; qq += 8) {
        float qreg[KD];
#pragma unroll
        for (int d = 0; d < KD; d++) qreg[d] = qs[qq * KD + d];

        float s[7];
        float mx = -1e30f;
#pragma unroll
        for (int it = 0; it < 7; it++) {
            int n = l + it * 32;
            float val = -1e30f;
            if (n < NTOK) {
                float a = 0.f;
#pragma unroll
                for (int d = 0; d < KD; d++)
                    a = fmaf(qreg[d], ks[n * KD + d], a);
                val = fmaf(a, ATTNSCALE, __ldg(bt + qq * NTOK + n));
            }
            s[it] = val;
            mx = fmaxf(mx, val);
        }
#pragma unroll
        for (int o = 16; o > 0; o >>= 1)
            mx = fmaxf(mx, __shfl_xor_sync(0xffffffffu, mx, o));

        float sum = 0.f;
        float e[7];
#pragma unroll
        for (int it = 0; it < 7; it++) {
            int n = l + it * 32;
            float ev = (n < NTOK) ? __expf(s[it] - mx) : 0.f;
            e[it] = ev;
            sum += ev;
        }
#pragma unroll
        for (int o = 16; o > 0; o >>= 1)
            sum += __shfl_xor_sync(0xffffffffu, sum, o);
        float inv = 1.f / sum;
#pragma unroll
        for (int it = 0; it < 7; it++) {
            int n = l + it * 32;
            if (n < NTOK) pbuf[w * NTOK + n] = e[it] * inv;
        }
        __syncwarp();

        float o = 0.f;
        const float* pr = &pbuf[w * NTOK];
#pragma unroll 4
        for (int n = 0; n < NTOK; n++)
            o = fmaf(pr[n], vs[n * VD + l], o);

        float so = o / (1.f + __expf(-o));
        ao[(size_t)(b * NQTOK + qq) * VALATTN + h * VD + l] = so;
        __syncwarp();
    }
}

// ---------------------------------------------------------------------------
// Launch
// ---------------------------------------------------------------------------
extern "C" void kernel_launch(void* const* d_in, const int* in_sizes, int n_in,
                              void* d_out, int out_size)
{
    const float* x     = (const float*)d_in[0];
    const float* kv_w  = (const float*)d_in[1];
    const float* kv_g  = (const float*)d_in[2];
    const float* kv_b  = (const float*)d_in[3];
    const float* kv_m  = (const float*)d_in[4];
    const float* kv_v  = (const float*)d_in[5];
    const float* q_w   = (const float*)d_in[6];
    const float* q_g   = (const float*)d_in[7];
    const float* q_b   = (const float*)d_in[8];
    const float* q_m   = (const float*)d_in[9];
    const float* q_v   = (const float*)d_in[10];
    const float* pj_w  = (const float*)d_in[11];
    const float* pj_g  = (const float*)d_in[12];
    const float* pj_b  = (const float*)d_in[13];
    const float* pj_m  = (const float*)d_in[14];
    const float* pj_v  = (const float*)d_in[15];
    const float* biases    = (const float*)d_in[16];
    const int*   bias_idxs = (const int*)d_in[17];
    float* out = (float*)d_out;

    float *kv_buf, *q_buf, *ao_buf, *btab;
    cudaGetSymbolAddress((void**)&kv_buf, g_kv);
    cudaGetSymbolAddress((void**)&q_buf,  g_q);
    cudaGetSymbolAddress((void**)&ao_buf, g_ao);
    cudaGetSymbolAddress((void**)&btab,   g_btab);

    // bias table precompute (tiny)
    bias_pre_kernel<<<(NQTOK * NTOK + 255) / 256, 256>>>(biases, bias_idxs, btab);

    // GEMM1: kv = BN(x @ kv_w^T)   [50176 x 576]
    gemm_tf32_bn<false><<<dim3(KVD / 64, M1 / 128), 256>>>(
        x, kv_w, kv_g, kv_b, kv_m, kv_v, kv_buf, KVD);

    // GEMM2: q = BN(xq @ q_w^T)    [12544 x 192], gathered rows
    gemm_tf32_bn<true><<<dim3(KEYATTN / 64, M2 / 128), 256>>>(
        x, q_w, q_g, q_b, q_m, q_v, q_buf, KEYATTN);

    // Attention + softmax + silu
    attn_kernel<<<BATCH * HEADS, 256>>>(kv_buf, q_buf, btab, ao_buf);

    // GEMM3: out = BN(silu_attn @ pj_w^T)  [12544 x 512]
    gemm_tf32_bn<false><<<dim3(OUTDIM / 64, M2 / 128), 256>>>(
        ao_buf, pj_w, pj_g, pj_b, pj_m, pj_v, out, OUTDIM);
}

// round 4
// speedup vs baseline: 1.9914x; 1.9914x over previous
#include <cuda_runtime.h>
#include <math.h>
#include <stdint.h>

// ---------------------------------------------------------------------------
// Problem constants
// ---------------------------------------------------------------------------
#define BATCH    256
#define RESOL    14
#define NTOK     196
#define NQTOK    49
#define INDIM    384
#define HEADS    12
#define KD       16
#define VD       32
#define KVD      576
#define KEYATTN  192
#define VALATTN  384
#define OUTDIM   512
#define ATTNSCALE 0.25f
#define BN_EPS   1e-5f

#define M1 (BATCH*NTOK)   // 50176
#define M2 (BATCH*NQTOK)  // 12544

// Scratch (device globals)
__device__ float g_kv[(size_t)M1 * KVD];
__device__ float g_q [(size_t)M2 * KEYATTN];
__device__ float g_ao[(size_t)M2 * VALATTN];
__device__ float g_btab[(size_t)HEADS * NQTOK * NTOK];

// ---------------------------------------------------------------------------
// tf32 helpers
// ---------------------------------------------------------------------------
__device__ __forceinline__ uint32_t f2tf32(float f) {
    uint32_t u;
    asm("cvt.rna.tf32.f32 %0, %1;" : "=r"(u) : "f"(f));
    return u;
}

__device__ __forceinline__ void mma_tf32(float* c, const uint32_t* a, const uint32_t* b) {
    asm volatile(
        "mma.sync.aligned.m16n8k8.row.col.f32.tf32.tf32.f32 "
        "{%0,%1,%2,%3}, {%4,%5,%6,%7}, {%8,%9}, {%0,%1,%2,%3};\n"
        : "+f"(c[0]), "+f"(c[1]), "+f"(c[2]), "+f"(c[3])
        : "r"(a[0]), "r"(a[1]), "r"(a[2]), "r"(a[3]), "r"(b[0]), "r"(b[1]));
}

// ---------------------------------------------------------------------------
// tf32 tensor-core GEMM + BatchNorm epilogue.
// ---------------------------------------------------------------------------
template<bool GATHER>
__global__ __launch_bounds__(256)
void gemm_tf32_bn(const float* __restrict__ A, const float* __restrict__ W,
                  const float* __restrict__ bn_g, const float* __restrict__ bn_b,
                  const float* __restrict__ bn_m, const float* __restrict__ bn_v,
                  float* __restrict__ C, int N)
{
    __shared__ uint32_t As[32][133];
    __shared__ uint32_t Bs[32][69];

    const int tid  = threadIdx.x;
    const int bm   = blockIdx.y * 128;
    const int bn   = blockIdx.x * 64;
    const int warp = tid >> 5;
    const int lane = tid & 31;
    const int wm   = (warp >> 1) * 32;
    const int wn   = (warp & 1) * 32;
    const int g8   = lane >> 2;
    const int tg   = lane & 3;

    const int lrow = tid >> 3;
    const int lcol = (tid & 7) * 4;

    int asrc[4];
#pragma unroll
    for (int r = 0; r < 4; r++) {
        int m = bm + lrow + r * 32;
        if (GATHER) {
            int b  = m / NQTOK;
            int qq = m - b * NQTOK;
            int qi = qq / 7;
            int qj = qq - qi * 7;
            asrc[r] = b * NTOK + qi * 2 * RESOL + qj * 2;
        } else {
            asrc[r] = m;
        }
    }
    int bsrc[2];
#pragma unroll
    for (int r = 0; r < 2; r++) bsrc[r] = bn + lrow + r * 32;

    float4 ar[4], br[2];

    auto gload = [&](int k0) {
#pragma unroll
        for (int r = 0; r < 4; r++)
            ar[r] = *(const float4*)(A + (size_t)asrc[r] * INDIM + k0 + lcol);
#pragma unroll
        for (int r = 0; r < 2; r++)
            br[r] = *(const float4*)(W + (size_t)bsrc[r] * INDIM + k0 + lcol);
    };
    auto stage = [&]() {
#pragma unroll
        for (int r = 0; r < 4; r++) {
            int row = lrow + r * 32;
            As[lcol + 0][row] = f2tf32(ar[r].x);
            As[lcol + 1][row] = f2tf32(ar[r].y);
            As[lcol + 2][row] = f2tf32(ar[r].z);
            As[lcol + 3][row] = f2tf32(ar[r].w);
        }
#pragma unroll
        for (int r = 0; r < 2; r++) {
            int row = lrow + r * 32;
            Bs[lcol + 0][row] = f2tf32(br[r].x);
            Bs[lcol + 1][row] = f2tf32(br[r].y);
            Bs[lcol + 2][row] = f2tf32(br[r].z);
            Bs[lcol + 3][row] = f2tf32(br[r].w);
        }
    };

    float acc[2][4][4] = {};

    gload(0);
    stage();
    __syncthreads();

    const int NIT = INDIM / 32;
    for (int it = 0; it < NIT; it++) {
        if (it + 1 < NIT) gload((it + 1) * 32);

#pragma unroll
        for (int ks = 0; ks < 4; ks++) {
            const int kb = ks * 8;
            uint32_t af[2][4];
#pragma unroll
            for (int mi = 0; mi < 2; mi++) {
                int m0 = wm + mi * 16 + g8;
                af[mi][0] = As[kb + tg    ][m0];
                af[mi][1] = As[kb + tg    ][m0 + 8];
                af[mi][2] = As[kb + tg + 4][m0];
                af[mi][3] = As[kb + tg + 4][m0 + 8];
            }
            uint32_t bf[4][2];
#pragma unroll
            for (int ni = 0; ni < 4; ni++) {
                int n0 = wn + ni * 8 + g8;
                bf[ni][0] = Bs[kb + tg    ][n0];
                bf[ni][1] = Bs[kb + tg + 4][n0];
            }
#pragma unroll
            for (int mi = 0; mi < 2; mi++)
#pragma unroll
                for (int ni = 0; ni < 4; ni++)
                    mma_tf32(acc[mi][ni], af[mi], bf[ni]);
        }
        __syncthreads();
        if (it + 1 < NIT) {
            stage();
            __syncthreads();
        }
    }

#pragma unroll
    for (int ni = 0; ni < 4; ni++) {
        int n0 = bn + wn + ni * 8 + 2 * tg;
        float sc0 = bn_g[n0] * rsqrtf(bn_v[n0] + BN_EPS);
        float bi0 = bn_b[n0] - bn_m[n0] * sc0;
        float sc1 = bn_g[n0 + 1] * rsqrtf(bn_v[n0 + 1] + BN_EPS);
        float bi1 = bn_b[n0 + 1] - bn_m[n0 + 1] * sc1;
#pragma unroll
        for (int mi = 0; mi < 2; mi++) {
#pragma unroll
            for (int rr = 0; rr < 2; rr++) {
                int mrow = bm + wm + mi * 16 + g8 + rr * 8;
                float2 val;
                val.x = fmaf(acc[mi][ni][rr * 2 + 0], sc0, bi0);
                val.y = fmaf(acc[mi][ni][rr * 2 + 1], sc1, bi1);
                *(float2*)(C + (size_t)mrow * N + n0) = val;
            }
        }
    }
}

// ---------------------------------------------------------------------------
// Precompute bias table: btab[h][q][n] = biases[h, bias_idxs[q,n]]
// ---------------------------------------------------------------------------
__global__ __launch_bounds__(256)
void bias_pre_kernel(const float* __restrict__ biases, const int* __restrict__ idxs,
                     float* __restrict__ tab)
{
    int i = blockIdx.x * 256 + threadIdx.x;
    if (i < NQTOK * NTOK) {
        int id = idxs[i];
#pragma unroll
        for (int h = 0; h < HEADS; h++)
            tab[(size_t)h * (NQTOK * NTOK) + i] = biases[h * NTOK + id];
    }
}

// ---------------------------------------------------------------------------
// Tensor-core attention. One block per (b,h), 256 threads = 8 warps.
// Smem (dynamic, u32 units):
//   Qs [64][17]   tf32 (rows 49..63 zero)
//   Ks [200][17]  tf32 (rows 196..199 zero)
//   Vt [32][201]  tf32 (cols 196..200 zero)
//   Sb [64][201]  f32 S, then tf32 P in place
// ---------------------------------------------------------------------------
#define LDQ 17
#define LDK 17
#define LDV 201
#define LDS_ 201
#define QS_OFF 0
#define KS_OFF (QS_OFF + 64*LDQ)
#define VT_OFF (KS_OFF + 200*LDK)
#define SB_OFF (VT_OFF + 32*LDV)
#define ATTN_SMEM_U32 (SB_OFF + 64*LDS_)
#define ATTN_SMEM_BYTES (ATTN_SMEM_U32 * 4)

__global__ __launch_bounds__(256)
void attn_tc_kernel(const float* __restrict__ kv, const float* __restrict__ qg,
                    const float* __restrict__ btab, float* __restrict__ ao)
{
    extern __shared__ uint32_t sm[];
    uint32_t* Qs = sm + QS_OFF;
    uint32_t* Ks = sm + KS_OFF;
    uint32_t* Vt = sm + VT_OFF;
    uint32_t* Sb = sm + SB_OFF;

    const int tid  = threadIdx.x;
    const int b    = blockIdx.x / HEADS;
    const int h    = blockIdx.x - b * HEADS;
    const int w    = tid >> 5;
    const int lane = tid & 31;
    const int g8   = lane >> 2;
    const int tg   = lane & 3;
    const float* bt = btab + (size_t)h * (NQTOK * NTOK);

    // ---- zero pad regions ----
    for (int i = tid; i < 64 * LDQ; i += 256) Qs[i] = 0;
    for (int i = tid; i < 200 * LDK; i += 256) Ks[i] = 0;
    for (int i = tid; i < 32 * 5; i += 256) {
        int d = i / 5, n = 196 + (i % 5);
        Vt[d * LDV + n] = 0;
    }
    __syncthreads();

    // ---- stage Q, K, V (tf32) ----
    for (int i = tid; i < NQTOK * KD; i += 256) {
        int qi = i >> 4, d = i & 15;
        Qs[qi * LDQ + d] = f2tf32(qg[(size_t)(b * NQTOK + qi) * KEYATTN + h * KD + d]);
    }
    for (int i = tid; i < NTOK * KD; i += 256) {
        int n = i >> 4, d = i & 15;
        Ks[n * LDK + d] = f2tf32(kv[(size_t)(b * NTOK + n) * KVD + h * (KD + VD) + d]);
    }
    for (int i = tid; i < NTOK * VD; i += 256) {
        int n = i >> 5, d = i & 31;
        Vt[d * LDV + n] = f2tf32(kv[(size_t)(b * NTOK + n) * KVD + h * (KD + VD) + KD + d]);
    }
    __syncthreads();

    // ---- S = Q K^T * SCALE + bias ----
    {
        const int mt = w >> 1;
        const int nh = w & 1;
        const int nt0 = nh ? 13 : 0;
        const int nt1 = nh ? 25 : 13;

        uint32_t a[2][4];
#pragma unroll
        for (int ks = 0; ks < 2; ks++) {
            int k0 = ks * 8;
            int r = mt * 16 + g8;
            a[ks][0] = Qs[r * LDQ + k0 + tg];
            a[ks][1] = Qs[(r + 8) * LDQ + k0 + tg];
            a[ks][2] = Qs[r * LDQ + k0 + tg + 4];
            a[ks][3] = Qs[(r + 8) * LDQ + k0 + tg + 4];
        }
        for (int nt = nt0; nt < nt1; nt++) {
            float c[4] = {0.f, 0.f, 0.f, 0.f};
#pragma unroll
            for (int ks = 0; ks < 2; ks++) {
                int k0 = ks * 8;
                uint32_t bfr[2];
                bfr[0] = Ks[(nt * 8 + g8) * LDK + k0 + tg];
                bfr[1] = Ks[(nt * 8 + g8) * LDK + k0 + tg + 4];
                mma_tf32(c, a[ks], bfr);
            }
            int r0 = mt * 16 + g8;
            int r1 = r0 + 8;
            int col = nt * 8 + 2 * tg;
            float2 bv0 = make_float2(0.f, 0.f), bv1 = make_float2(0.f, 0.f);
            if (col < NTOK) {
                if (r0 < NQTOK) bv0 = *(const float2*)(bt + r0 * NTOK + col);
                if (r1 < NQTOK) bv1 = *(const float2*)(bt + r1 * NTOK + col);
            }
            Sb[r0 * LDS_ + col]     = __float_as_uint(fmaf(c[0], ATTNSCALE, bv0.x));
            Sb[r0 * LDS_ + col + 1] = __float_as_uint(fmaf(c[1], ATTNSCALE, bv0.y));
            Sb[r1 * LDS_ + col]     = __float_as_uint(fmaf(c[2], ATTNSCALE, bv1.x));
            Sb[r1 * LDS_ + col + 1] = __float_as_uint(fmaf(c[3], ATTNSCALE, bv1.y));
        }
    }
    __syncthreads();

    // ---- softmax rows, write P as tf32 in place ----
    for (int r = w; r < NQTOK; r += 8) {
        float s[7];
        float mx = -1e30f;
#pragma unroll
        for (int it = 0; it < 7; it++) {
            int n = lane + it * 32;
            float v = (n < NTOK) ? __uint_as_float(Sb[r * LDS_ + n]) : -1e30f;
            s[it] = v;
            mx = fmaxf(mx, v);
        }
#pragma unroll
        for (int o = 16; o > 0; o >>= 1)
            mx = fmaxf(mx, __shfl_xor_sync(0xffffffffu, mx, o));
        float sum = 0.f;
        float e[7];
#pragma unroll
        for (int it = 0; it < 7; it++) {
            int n = lane + it * 32;
            float ev = (n < NTOK) ? __expf(s[it] - mx) : 0.f;
            e[it] = ev;
            sum += ev;
        }
#pragma unroll
        for (int o = 16; o > 0; o >>= 1)
            sum += __shfl_xor_sync(0xffffffffu, sum, o);
        float inv = 1.f / sum;
#pragma unroll
        for (int it = 0; it < 7; it++) {
            int n = lane + it * 32;
            if (n < NTOK)      Sb[r * LDS_ + n] = f2tf32(e[it] * inv);
            else if (n < 200)  Sb[r * LDS_ + n] = 0;
        }
    }
    __syncthreads();

    // ---- O = P V, silu, store ----
    {
        const int mt = w >> 1;
        const int ntb = (w & 1) * 2;
        float acc[2][4] = {};
        for (int ks = 0; ks < 25; ks++) {
            int k0 = ks * 8;
            uint32_t a[4];
            int r = mt * 16 + g8;
            a[0] = Sb[r * LDS_ + k0 + tg];
            a[1] = Sb[(r + 8) * LDS_ + k0 + tg];
            a[2] = Sb[r * LDS_ + k0 + tg + 4];
            a[3] = Sb[(r + 8) * LDS_ + k0 + tg + 4];
#pragma unroll
            for (int t = 0; t < 2; t++) {
                int nt = ntb + t;
                uint32_t bfr[2];
                bfr[0] = Vt[(nt * 8 + g8) * LDV + k0 + tg];
                bfr[1] = Vt[(nt * 8 + g8) * LDV + k0 + tg + 4];
                mma_tf32(acc[t], a, bfr);
            }
        }
#pragma unroll
        for (int t = 0; t < 2; t++) {
            int nt = ntb + t;
            int d0 = nt * 8 + 2 * tg;
            int q0 = mt * 16 + g8;
            int q1 = q0 + 8;
            if (q0 < NQTOK) {
                float o0 = acc[t][0], o1 = acc[t][1];
                float2 v;
                v.x = o0 / (1.f + __expf(-o0));
                v.y = o1 / (1.f + __expf(-o1));
                *(float2*)(ao + (size_t)(b * NQTOK + q0) * VALATTN + h * VD + d0) = v;
            }
            if (q1 < NQTOK) {
                float o0 = acc[t][2], o1 = acc[t][3];
                float2 v;
                v.x = o0 / (1.f + __expf(-o0));
                v.y = o1 / (1.f + __expf(-o1));
                *(float2*)(ao + (size_t)(b * NQTOK + q1) * VALATTN + h * VD + d0) = v;
            }
        }
    }
}

// ---------------------------------------------------------------------------
// Launch
// ---------------------------------------------------------------------------
extern "C" void kernel_launch(void* const* d_in, const int* in_sizes, int n_in,
                              void* d_out, int out_size)
{
    const float* x     = (const float*)d_in[0];
    const float* kv_w  = (const float*)d_in[1];
    const float* kv_g  = (const float*)d_in[2];
    const float* kv_b  = (const float*)d_in[3];
    const float* kv_m  = (const float*)d_in[4];
    const float* kv_v  = (const float*)d_in[5];
    const float* q_w   = (const float*)d_in[6];
    const float* q_g   = (const float*)d_in[7];
    const float* q_b   = (const float*)d_in[8];
    const float* q_m   = (const float*)d_in[9];
    const float* q_v   = (const float*)d_in[10];
    const float* pj_w  = (const float*)d_in[11];
    const float* pj_g  = (const float*)d_in[12];
    const float* pj_b  = (const float*)d_in[13];
    const float* pj_m  = (const float*)d_in[14];
    const float* pj_v  = (const float*)d_in[15];
    const float* biases    = (const float*)d_in[16];
    const int*   bias_idxs = (const int*)d_in[17];
    float* out = (float*)d_out;

    float *kv_buf, *q_buf, *ao_buf, *btab;
    cudaGetSymbolAddress((void**)&kv_buf, g_kv);
    cudaGetSymbolAddress((void**)&q_buf,  g_q);
    cudaGetSymbolAddress((void**)&ao_buf, g_ao);
    cudaGetSymbolAddress((void**)&btab,   g_btab);

    cudaFuncSetAttribute(attn_tc_kernel,
                         cudaFuncAttributeMaxDynamicSharedMemorySize,
                         ATTN_SMEM_BYTES);

    bias_pre_kernel<<<(NQTOK * NTOK + 255) / 256, 256>>>(biases, bias_idxs, btab);

    gemm_tf32_bn<false><<<dim3(KVD / 64, M1 / 128), 256>>>(
        x, kv_w, kv_g, kv_b, kv_m, kv_v, kv_buf, KVD);

    gemm_tf32_bn<true><<<dim3(KEYATTN / 64, M2 / 128), 256>>>(
        x, q_w, q_g, q_b, q_m, q_v, q_buf, KEYATTN);

    attn_tc_kernel<<<BATCH * HEADS, 256, ATTN_SMEM_BYTES>>>(
        kv_buf, q_buf, btab, ao_buf);

    gemm_tf32_bn<false><<<dim3(OUTDIM / 64, M2 / 128), 256>>>(
        ao_buf, pj_w, pj_g, pj_b, pj_m, pj_v, out, OUTDIM);
}

// round 5
// speedup vs baseline: 2.2110x; 1.1103x over previous
#include <cuda_runtime.h>
#include <math.h>
#include <stdint.h>

// ---------------------------------------------------------------------------
// Problem constants
// ---------------------------------------------------------------------------
#define BATCH    256
#define RESOL    14
#define NTOK     196
#define NQTOK    49
#define INDIM    384
#define HEADS    12
#define KD       16
#define VD       32
#define KVD      576
#define KEYATTN  192
#define VALATTN  384
#define OUTDIM   512
#define ATTNSCALE 0.25f
#define BN_EPS   1e-5f

#define M1 (BATCH*NTOK)   // 50176
#define M2 (BATCH*NQTOK)  // 12544

// Weight offsets inside g_wr (rows of 384)
#define WR_KV 0
#define WR_Q  (576*INDIM)
#define WR_PJ (768*INDIM)

// Scratch (device globals)
__device__ float g_kv[(size_t)M1 * KVD];
__device__ float g_q [(size_t)M2 * KEYATTN];
__device__ float g_ao[(size_t)M2 * VALATTN];
__device__ float g_btab[(size_t)HEADS * NQTOK * NTOK];
__device__ float g_xr [(size_t)M1 * INDIM];        // tf32-rounded x
__device__ float g_wr [(size_t)1280 * INDIM];      // tf32-rounded weights

// ---------------------------------------------------------------------------
// tf32 / mma / cp.async helpers
// ---------------------------------------------------------------------------
__device__ __forceinline__ uint32_t f2tf32(float f) {
    uint32_t u;
    asm("cvt.rna.tf32.f32 %0, %1;" : "=r"(u) : "f"(f));
    return u;
}

__device__ __forceinline__ void mma_tf32(float* c, const uint32_t* a, const uint32_t* b) {
    asm volatile(
        "mma.sync.aligned.m16n8k8.row.col.f32.tf32.tf32.f32 "
        "{%0,%1,%2,%3}, {%4,%5,%6,%7}, {%8,%9}, {%0,%1,%2,%3};\n"
        : "+f"(c[0]), "+f"(c[1]), "+f"(c[2]), "+f"(c[3])
        : "r"(a[0]), "r"(a[1]), "r"(a[2]), "r"(a[3]), "r"(b[0]), "r"(b[1]));
}

__device__ __forceinline__ void cp_async16(uint32_t dst, const void* src) {
    asm volatile("cp.async.cg.shared.global [%0], [%1], 16;\n" :: "r"(dst), "l"(src));
}
__device__ __forceinline__ void cp_commit() {
    asm volatile("cp.async.commit_group;\n" ::: "memory");
}

// ---------------------------------------------------------------------------
// Pre-round to tf32 (RNA) so the GEMMs can consume raw bits via cp.async.
// ---------------------------------------------------------------------------
__global__ __launch_bounds__(256)
void round_tf32_kernel(const float4* __restrict__ in, float4* __restrict__ out, int n4)
{
    int i = blockIdx.x * 256 + threadIdx.x;
    if (i < n4) {
        float4 v = in[i];
        float4 o;
        o.x = __uint_as_float(f2tf32(v.x));
        o.y = __uint_as_float(f2tf32(v.y));
        o.z = __uint_as_float(f2tf32(v.z));
        o.w = __uint_as_float(f2tf32(v.w));
        out[i] = o;
    }
}

// ---------------------------------------------------------------------------
// cp.async 3-stage tf32 GEMM + BN epilogue.
// A [M,384] and W [N,384] are PRE-ROUNDED to tf32 bits.
// Tile BM=128, BN=64, BK=32; 256 threads = 8 warps (4m x 2n), 32x32/warp.
// Smem row-major with pad 36 (banks 4*g8+tg -> conflict-free frags).
// One __syncthreads per K-iteration.
// ---------------------------------------------------------------------------
#define GBK 32
#define GLDA 36
#define GLDB 36
#define A_STAGE (128*GLDA)                 // 4608 words
#define B_STAGE (64*GLDB)                  // 2304 words
#define STAGE_W (A_STAGE + B_STAGE)        // 6912 words
#define GEMM_SMEM_BYTES (3*STAGE_W*4)      // 82944 bytes

template<bool GATHER>
__global__ __launch_bounds__(256)
void gemm_cp_bn(const float* __restrict__ A, const float* __restrict__ W,
                const float* __restrict__ bn_g, const float* __restrict__ bn_b,
                const float* __restrict__ bn_m, const float* __restrict__ bn_v,
                float* __restrict__ C, int N)
{
    extern __shared__ uint32_t gsm[];

    const int tid  = threadIdx.x;
    const int bm   = blockIdx.y * 128;
    const int bn   = blockIdx.x * 64;
    const int warp = tid >> 5;
    const int lane = tid & 31;
    const int wm   = (warp >> 1) * 32;
    const int wn   = (warp & 1) * 32;
    const int g8   = lane >> 2;
    const int tg   = lane & 3;

    const int lrow = tid >> 3;        // 0..31
    const int seg  = tid & 7;         // 16B segment (4 floats)

    int asrc[4];
#pragma unroll
    for (int j = 0; j < 4; j++) {
        int m = bm + lrow + 32 * j;
        if (GATHER) {
            int b  = m / NQTOK;
            int qq = m - b * NQTOK;
            int qi = qq / 7;
            int qj = qq - qi * 7;
            asrc[j] = b * NTOK + qi * 2 * RESOL + qj * 2;
        } else {
            asrc[j] = m;
        }
    }
    int bsrc[2];
#pragma unroll
    for (int j = 0; j < 2; j++) bsrc[j] = bn + lrow + 32 * j;

    const uint32_t sbase = (uint32_t)__cvta_generic_to_shared(gsm);

    auto issue = [&](int it, int s) {
        const int k0 = it * GBK;
        uint32_t abase = sbase + (uint32_t)(s * STAGE_W) * 4u;
#pragma unroll
        for (int j = 0; j < 4; j++) {
            uint32_t dst = abase + (uint32_t)((lrow + 32 * j) * GLDA + seg * 4) * 4u;
            cp_async16(dst, A + (size_t)asrc[j] * INDIM + k0 + seg * 4);
        }
        uint32_t bbase = abase + (uint32_t)A_STAGE * 4u;
#pragma unroll
        for (int j = 0; j < 2; j++) {
            uint32_t dst = bbase + (uint32_t)((lrow + 32 * j) * GLDB + seg * 4) * 4u;
            cp_async16(dst, W + (size_t)bsrc[j] * INDIM + k0 + seg * 4);
        }
        cp_commit();
    };

    float acc[2][4][4] = {};

    issue(0, 0);
    issue(1, 1);

    const int NIT = INDIM / GBK;   // 12
    for (int it = 0; it < NIT; it++) {
        if (it < NIT - 1) asm volatile("cp.async.wait_group 1;\n" ::: "memory");
        else              asm volatile("cp.async.wait_group 0;\n" ::: "memory");
        __syncthreads();
        if (it + 2 < NIT) issue(it + 2, (it + 2) % 3);

        const uint32_t* As = gsm + (it % 3) * STAGE_W;
        const uint32_t* Bs = As + A_STAGE;

#pragma unroll
        for (int kc = 0; kc < 4; kc++) {
            const int kb = kc * 8;
            uint32_t af[2][4];
#pragma unroll
            for (int mi = 0; mi < 2; mi++) {
                int m0 = wm + mi * 16 + g8;
                af[mi][0] = As[m0 * GLDA + kb + tg];
                af[mi][1] = As[(m0 + 8) * GLDA + kb + tg];
                af[mi][2] = As[m0 * GLDA + kb + tg + 4];
                af[mi][3] = As[(m0 + 8) * GLDA + kb + tg + 4];
            }
            uint32_t bf[4][2];
#pragma unroll
            for (int ni = 0; ni < 4; ni++) {
                int n0 = wn + ni * 8 + g8;
                bf[ni][0] = Bs[n0 * GLDB + kb + tg];
                bf[ni][1] = Bs[n0 * GLDB + kb + tg + 4];
            }
#pragma unroll
            for (int mi = 0; mi < 2; mi++)
#pragma unroll
                for (int ni = 0; ni < 4; ni++)
                    mma_tf32(acc[mi][ni], af[mi], bf[ni]);
        }
    }

    // BN epilogue
#pragma unroll
    for (int ni = 0; ni < 4; ni++) {
        int n0 = bn + wn + ni * 8 + 2 * tg;
        float sc0 = bn_g[n0] * rsqrtf(bn_v[n0] + BN_EPS);
        float bi0 = bn_b[n0] - bn_m[n0] * sc0;
        float sc1 = bn_g[n0 + 1] * rsqrtf(bn_v[n0 + 1] + BN_EPS);
        float bi1 = bn_b[n0 + 1] - bn_m[n0 + 1] * sc1;
#pragma unroll
        for (int mi = 0; mi < 2; mi++) {
#pragma unroll
            for (int rr = 0; rr < 2; rr++) {
                int mrow = bm + wm + mi * 16 + g8 + rr * 8;
                float2 val;
                val.x = fmaf(acc[mi][ni][rr * 2 + 0], sc0, bi0);
                val.y = fmaf(acc[mi][ni][rr * 2 + 1], sc1, bi1);
                *(float2*)(C + (size_t)mrow * N + n0) = val;
            }
        }
    }
}

// ---------------------------------------------------------------------------
// Precompute bias table: btab[h][q][n] = biases[h, bias_idxs[q,n]]
// ---------------------------------------------------------------------------
__global__ __launch_bounds__(256)
void bias_pre_kernel(const float* __restrict__ biases, const int* __restrict__ idxs,
                     float* __restrict__ tab)
{
    int i = blockIdx.x * 256 + threadIdx.x;
    if (i < NQTOK * NTOK) {
        int id = idxs[i];
#pragma unroll
        for (int h = 0; h < HEADS; h++)
            tab[(size_t)h * (NQTOK * NTOK) + i] = biases[h * NTOK + id];
    }
}

// ---------------------------------------------------------------------------
// Tensor-core attention, SPLIT: 2 blocks per (b,h), 32 q-rows each.
// 256 threads = 8 warps. Smem 67 KB -> 3 CTA/SM.
// Output written tf32-rounded (GEMM3 consumes raw).
// ---------------------------------------------------------------------------
#define LDQ 17
#define LDK 17
#define LDV 201
#define LDS_ 201
#define QROWS 32
#define QS_OFF 0
#define KS_OFF (QS_OFF + QROWS*LDQ)          // 544
#define VT_OFF (KS_OFF + 200*LDK)            // 3944
#define SB_OFF (VT_OFF + 32*LDV)             // 10376
#define ATTN_SMEM_U32 (SB_OFF + QROWS*LDS_)  // 16808
#define ATTN_SMEM_BYTES (ATTN_SMEM_U32 * 4)  // 67232

__global__ __launch_bounds__(256)
void attn_tc_kernel(const float* __restrict__ kv, const float* __restrict__ qg,
                    const float* __restrict__ btab, float* __restrict__ ao)
{
    extern __shared__ uint32_t sm[];
    uint32_t* Qs = sm + QS_OFF;
    uint32_t* Ks = sm + KS_OFF;
    uint32_t* Vt = sm + VT_OFF;
    uint32_t* Sb = sm + SB_OFF;

    const int tid   = threadIdx.x;
    const int half  = blockIdx.x & 1;
    const int bh    = blockIdx.x >> 1;
    const int b     = bh / HEADS;
    const int h     = bh - b * HEADS;
    const int qbase = half * QROWS;
    const int w     = tid >> 5;
    const int lane  = tid & 31;
    const int g8    = lane >> 2;
    const int tg    = lane & 3;
    const float* bt = btab + (size_t)h * (NQTOK * NTOK);

    // ---- zero pad regions ----
    for (int i = tid; i < QROWS * LDQ; i += 256) Qs[i] = 0;
    for (int i = tid; i < 200 * LDK; i += 256) Ks[i] = 0;
    for (int i = tid; i < 32 * 5; i += 256) {
        int d = i / 5, n = 196 + (i % 5);
        Vt[d * LDV + n] = 0;
    }
    __syncthreads();

    // ---- stage Q (32 rows, guarded), K, V ----
    for (int i = tid; i < QROWS * KD; i += 256) {
        int qi = i >> 4, d = i & 15;
        if (qbase + qi < NQTOK)
            Qs[qi * LDQ + d] =
                f2tf32(qg[(size_t)(b * NQTOK + qbase + qi) * KEYATTN + h * KD + d]);
    }
    for (int i = tid; i < NTOK * KD; i += 256) {
        int n = i >> 4, d = i & 15;
        Ks[n * LDK + d] = f2tf32(kv[(size_t)(b * NTOK + n) * KVD + h * (KD + VD) + d]);
    }
    for (int i = tid; i < NTOK * VD; i += 256) {
        int n = i >> 5, d = i & 31;
        Vt[d * LDV + n] = f2tf32(kv[(size_t)(b * NTOK + n) * KVD + h * (KD + VD) + KD + d]);
    }
    __syncthreads();

    // ---- S = Q K^T * SCALE + bias ----  warp w: mt = w>>2 (2 tiles), nq = w&3
    {
        const int mt = w >> 2;
        const int nq = w & 3;
        const int nt0 = (nq == 0) ? 0 : (nq == 1) ? 6 : (nq == 2) ? 12 : 18;
        const int nt1 = (nq == 0) ? 6 : (nq == 1) ? 12 : (nq == 2) ? 18 : 25;

        uint32_t a[2][4];
#pragma unroll
        for (int ks = 0; ks < 2; ks++) {
            int k0 = ks * 8;
            int r = mt * 16 + g8;
            a[ks][0] = Qs[r * LDQ + k0 + tg];
            a[ks][1] = Qs[(r + 8) * LDQ + k0 + tg];
            a[ks][2] = Qs[r * LDQ + k0 + tg + 4];
            a[ks][3] = Qs[(r + 8) * LDQ + k0 + tg + 4];
        }
        for (int nt = nt0; nt < nt1; nt++) {
            float c[4] = {0.f, 0.f, 0.f, 0.f};
#pragma unroll
            for (int ks = 0; ks < 2; ks++) {
                int k0 = ks * 8;
                uint32_t bfr[2];
                bfr[0] = Ks[(nt * 8 + g8) * LDK + k0 + tg];
                bfr[1] = Ks[(nt * 8 + g8) * LDK + k0 + tg + 4];
                mma_tf32(c, a[ks], bfr);
            }
            int r0 = mt * 16 + g8;          // local rows
            int r1 = r0 + 8;
            int gq0 = qbase + r0;           // global q rows
            int gq1 = qbase + r1;
            int col = nt * 8 + 2 * tg;
            float2 bv0 = make_float2(0.f, 0.f), bv1 = make_float2(0.f, 0.f);
            if (col < NTOK) {
                if (gq0 < NQTOK) bv0 = *(const float2*)(bt + gq0 * NTOK + col);
                if (gq1 < NQTOK) bv1 = *(const float2*)(bt + gq1 * NTOK + col);
            }
            Sb[r0 * LDS_ + col]     = __float_as_uint(fmaf(c[0], ATTNSCALE, bv0.x));
            Sb[r0 * LDS_ + col + 1] = __float_as_uint(fmaf(c[1], ATTNSCALE, bv0.y));
            Sb[r1 * LDS_ + col]     = __float_as_uint(fmaf(c[2], ATTNSCALE, bv1.x));
            Sb[r1 * LDS_ + col + 1] = __float_as_uint(fmaf(c[3], ATTNSCALE, bv1.y));
        }
    }
    __syncthreads();

    // ---- softmax rows (warp per row), write P as tf32 in place ----
    for (int r = w; r < QROWS; r += 8) {
        float s[7];
        float mx = -1e30f;
#pragma unroll
        for (int it = 0; it < 7; it++) {
            int n = lane + it * 32;
            float v = (n < NTOK) ? __uint_as_float(Sb[r * LDS_ + n]) : -1e30f;
            s[it] = v;
            mx = fmaxf(mx, v);
        }
#pragma unroll
        for (int o = 16; o > 0; o >>= 1)
            mx = fmaxf(mx, __shfl_xor_sync(0xffffffffu, mx, o));
        float sum = 0.f;
        float e[7];
#pragma unroll
        for (int it = 0; it < 7; it++) {
            int n = lane + it * 32;
            float ev = (n < NTOK) ? __expf(s[it] - mx) : 0.f;
            e[it] = ev;
            sum += ev;
        }
#pragma unroll
        for (int o = 16; o > 0; o >>= 1)
            sum += __shfl_xor_sync(0xffffffffu, sum, o);
        float inv = 1.f / sum;
#pragma unroll
        for (int it = 0; it < 7; it++) {
            int n = lane + it * 32;
            if (n < NTOK)      Sb[r * LDS_ + n] = f2tf32(e[it] * inv);
            else if (n < 200)  Sb[r * LDS_ + n] = 0;
        }
    }
    __syncthreads();

    // ---- O = P V, silu, store (tf32-rounded) ----  warp w: mt = w>>2, dh = w&3
    {
        const int mt = w >> 2;
        const int dh = w & 3;
        float acc[4] = {0.f, 0.f, 0.f, 0.f};
        for (int ks = 0; ks < 25; ks++) {
            int k0 = ks * 8;
            uint32_t a[4];
            int r = mt * 16 + g8;
            a[0] = Sb[r * LDS_ + k0 + tg];
            a[1] = Sb[(r + 8) * LDS_ + k0 + tg];
            a[2] = Sb[r * LDS_ + k0 + tg + 4];
            a[3] = Sb[(r + 8) * LDS_ + k0 + tg + 4];
            uint32_t bfr[2];
            bfr[0] = Vt[(dh * 8 + g8) * LDV + k0 + tg];
            bfr[1] = Vt[(dh * 8 + g8) * LDV + k0 + tg + 4];
            mma_tf32(acc, a, bfr);
        }
        int d0  = dh * 8 + 2 * tg;
        int gq0 = qbase + mt * 16 + g8;
        int gq1 = gq0 + 8;
        if (gq0 < NQTOK) {
            float o0 = acc[0], o1 = acc[1];
            float2 v;
            v.x = __uint_as_float(f2tf32(o0 / (1.f + __expf(-o0))));
            v.y = __uint_as_float(f2tf32(o1 / (1.f + __expf(-o1))));
            *(float2*)(ao + (size_t)(b * NQTOK + gq0) * VALATTN + h * VD + d0) = v;
        }
        if (gq1 < NQTOK) {
            float o0 = acc[2], o1 = acc[3];
            float2 v;
            v.x = __uint_as_float(f2tf32(o0 / (1.f + __expf(-o0))));
            v.y = __uint_as_float(f2tf32(o1 / (1.f + __expf(-o1))));
            *(float2*)(ao + (size_t)(b * NQTOK + gq1) * VALATTN + h * VD + d0) = v;
        }
    }
}

// ---------------------------------------------------------------------------
// Launch
// ---------------------------------------------------------------------------
extern "C" void kernel_launch(void* const* d_in, const int* in_sizes, int n_in,
                              void* d_out, int out_size)
{
    const float* x     = (const float*)d_in[0];
    const float* kv_w  = (const float*)d_in[1];
    const float* kv_g  = (const float*)d_in[2];
    const float* kv_b  = (const float*)d_in[3];
    const float* kv_m  = (const float*)d_in[4];
    const float* kv_v  = (const float*)d_in[5];
    const float* q_w   = (const float*)d_in[6];
    const float* q_g   = (const float*)d_in[7];
    const float* q_b   = (const float*)d_in[8];
    const float* q_m   = (const float*)d_in[9];
    const float* q_v   = (const float*)d_in[10];
    const float* pj_w  = (const float*)d_in[11];
    const float* pj_g  = (const float*)d_in[12];
    const float* pj_b  = (const float*)d_in[13];
    const float* pj_m  = (const float*)d_in[14];
    const float* pj_v  = (const float*)d_in[15];
    const float* biases    = (const float*)d_in[16];
    const int*   bias_idxs = (const int*)d_in[17];
    float* out = (float*)d_out;

    float *kv_buf, *q_buf, *ao_buf, *btab, *xr, *wr;
    cudaGetSymbolAddress((void**)&kv_buf, g_kv);
    cudaGetSymbolAddress((void**)&q_buf,  g_q);
    cudaGetSymbolAddress((void**)&ao_buf, g_ao);
    cudaGetSymbolAddress((void**)&btab,   g_btab);
    cudaGetSymbolAddress((void**)&xr,     g_xr);
    cudaGetSymbolAddress((void**)&wr,     g_wr);

    cudaFuncSetAttribute(attn_tc_kernel,
                         cudaFuncAttributeMaxDynamicSharedMemorySize, ATTN_SMEM_BYTES);
    cudaFuncSetAttribute(gemm_cp_bn<false>,
                         cudaFuncAttributeMaxDynamicSharedMemorySize, GEMM_SMEM_BYTES);
    cudaFuncSetAttribute(gemm_cp_bn<true>,
                         cudaFuncAttributeMaxDynamicSharedMemorySize, GEMM_SMEM_BYTES);

    // Pre-round inputs/weights to tf32 (RNA)
    {
        int n4 = (M1 * INDIM) / 4;
        round_tf32_kernel<<<(n4 + 255) / 256, 256>>>((const float4*)x, (float4*)xr, n4);
        int nkv = (KVD * INDIM) / 4;
        round_tf32_kernel<<<(nkv + 255) / 256, 256>>>((const float4*)kv_w, (float4*)(wr + WR_KV), nkv);
        int nq = (KEYATTN * INDIM) / 4;
        round_tf32_kernel<<<(nq + 255) / 256, 256>>>((const float4*)q_w, (float4*)(wr + WR_Q), nq);
        int npj = (OUTDIM * INDIM) / 4;
        round_tf32_kernel<<<(npj + 255) / 256, 256>>>((const float4*)pj_w, (float4*)(wr + WR_PJ), npj);
    }

    bias_pre_kernel<<<(NQTOK * NTOK + 255) / 256, 256>>>(biases, bias_idxs, btab);

    // GEMM1: kv = BN(x @ kv_w^T)   [50176 x 576]
    gemm_cp_bn<false><<<dim3(KVD / 64, M1 / 128), 256, GEMM_SMEM_BYTES>>>(
        xr, wr + WR_KV, kv_g, kv_b, kv_m, kv_v, kv_buf, KVD);

    // GEMM2: q = BN(xq @ q_w^T)    [12544 x 192], gathered rows
    gemm_cp_bn<true><<<dim3(KEYATTN / 64, M2 / 128), 256, GEMM_SMEM_BYTES>>>(
        xr, wr + WR_Q, q_g, q_b, q_m, q_v, q_buf, KEYATTN);

    // Attention (split: 2 blocks per (b,h))
    attn_tc_kernel<<<BATCH * HEADS * 2, 256, ATTN_SMEM_BYTES>>>(
        kv_buf, q_buf, btab, ao_buf);

    // GEMM3: out = BN(silu_attn @ pj_w^T)  [12544 x 512]
    gemm_cp_bn<false><<<dim3(OUTDIM / 64, M2 / 128), 256, GEMM_SMEM_BYTES>>>(
        ao_buf, wr + WR_PJ, pj_g, pj_b, pj_m, pj_v, out, OUTDIM);
}

// round 10
// speedup vs baseline: 2.7123x; 1.2268x over previous
#include <cuda_runtime.h>
#include <cuda_fp16.h>
#include <math.h>
#include <stdint.h>

// ---------------------------------------------------------------------------
// Problem constants
// ---------------------------------------------------------------------------
#define BATCH    256
#define RESOL    14
#define NTOK     196
#define NQTOK    49
#define INDIM    384
#define HEADS    12
#define KD       16
#define VD       32
#define KVD      576
#define KEYATTN  192
#define VALATTN  384
#define OUTDIM   512
#define ATTNSCALE 0.25f
#define BN_EPS   1e-5f

#define M1 (BATCH*NTOK)   // 50176
#define M2 (BATCH*NQTOK)  // 12544

// Weight offsets inside g_wh (rows of 384)
#define WR_KV 0
#define WR_Q  (576*INDIM)
#define WR_PJ (768*INDIM)

// Scratch (device globals)
__device__ float  g_kv[(size_t)M1 * KVD];
__device__ float  g_q [(size_t)M2 * KEYATTN];
__device__ __half g_aoh[(size_t)M2 * VALATTN];     // fp16 attention output
__device__ float  g_btab[(size_t)HEADS * NQTOK * NTOK];
__device__ __half g_xh [(size_t)M1 * INDIM];       // fp16 x
__device__ __half g_wh [(size_t)1280 * INDIM];     // fp16 weights

// ---------------------------------------------------------------------------
// helpers
// ---------------------------------------------------------------------------
__device__ __forceinline__ uint32_t f2tf32(float f) {
    uint32_t u;
    asm("cvt.rna.tf32.f32 %0, %1;" : "=r"(u) : "f"(f));
    return u;
}

__device__ __forceinline__ void mma_tf32(float* c, const uint32_t* a, const uint32_t* b) {
    asm volatile(
        "mma.sync.aligned.m16n8k8.row.col.f32.tf32.tf32.f32 "
        "{%0,%1,%2,%3}, {%4,%5,%6,%7}, {%8,%9}, {%0,%1,%2,%3};\n"
        : "+f"(c[0]), "+f"(c[1]), "+f"(c[2]), "+f"(c[3])
        : "r"(a[0]), "r"(a[1]), "r"(a[2]), "r"(a[3]), "r"(b[0]), "r"(b[1]));
}

__device__ __forceinline__ void mma_f16(float* c, const uint32_t* a, const uint32_t* b) {
    asm volatile(
        "mma.sync.aligned.m16n8k16.row.col.f32.f16.f16.f32 "
        "{%0,%1,%2,%3}, {%4,%5,%6,%7}, {%8,%9}, {%0,%1,%2,%3};\n"
        : "+f"(c[0]), "+f"(c[1]), "+f"(c[2]), "+f"(c[3])
        : "r"(a[0]), "r"(a[1]), "r"(a[2]), "r"(a[3]), "r"(b[0]), "r"(b[1]));
}

__device__ __forceinline__ void cp_async16(uint32_t dst, const void* src) {
    asm volatile("cp.async.cg.shared.global [%0], [%1], 16;\n" :: "r"(dst), "l"(src));
}
__device__ __forceinline__ void cp_commit() {
    asm volatile("cp.async.commit_group;\n" ::: "memory");
}

// ---------------------------------------------------------------------------
// f32 -> f16 conversion (RN)
// ---------------------------------------------------------------------------
__global__ __launch_bounds__(256)
void f32_to_f16_kernel(const float4* __restrict__ in, uint2* __restrict__ out, int n4)
{
    int i = blockIdx.x * 256 + threadIdx.x;
    if (i < n4) {
        float4 v = in[i];
        __half2 h0 = __floats2half2_rn(v.x, v.y);
        __half2 h1 = __floats2half2_rn(v.z, v.w);
        uint2 o;
        o.x = *(uint32_t*)&h0;
        o.y = *(uint32_t*)&h1;
        out[i] = o;
    }
}

// ---------------------------------------------------------------------------
// cp.async 3-stage fp16 GEMM + BN epilogue (structure = R5 passing kernel,
// data width halved; mma m16n8k16.f16 with fp32 accumulate).
// A [M,384] fp16, W [N,384] fp16. Tile BM=128, BN=64, BK=32 (halfs).
// Smem u32 view: row stride 20 (16 data + 4 pad) -> conflict-free frag loads.
// ---------------------------------------------------------------------------
#define HLD 20
#define HA_STAGE (128*HLD)                  // 2560 u32
#define HB_STAGE (64*HLD)                   // 1280 u32
#define HSTAGE_W (HA_STAGE + HB_STAGE)      // 3840 u32
#define GEMM_SMEM_BYTES (3*HSTAGE_W*4)      // 46080 B

template<bool GATHER>
__global__ __launch_bounds__(256)
void gemm_h_bn(const __half* __restrict__ A, const __half* __restrict__ W,
               const float* __restrict__ bn_g, const float* __restrict__ bn_b,
               const float* __restrict__ bn_m, const float* __restrict__ bn_v,
               float* __restrict__ C, int N)
{
    extern __shared__ uint32_t gsm[];

    const int tid  = threadIdx.x;
    const int bm   = blockIdx.y * 128;
    const int bn   = blockIdx.x * 64;
    const int warp = tid >> 5;
    const int lane = tid & 31;
    const int wm   = (warp >> 1) * 32;
    const int wn   = (warp & 1) * 32;
    const int g8   = lane >> 2;
    const int tg   = lane & 3;

    // cp.async mapping: 16B chunks; A: 128 rows x 4 chunks = 512 -> 2/thread
    // (256 threads). row = idx>>2, seg = idx&3, idx = tid + j*256.
    const int lrow = tid >> 2;        // 0..63
    const int seg  = tid & 3;

    int asrc[2];
#pragma unroll
    for (int j = 0; j < 2; j++) {
        int m = bm + lrow + 64 * j;
        if (GATHER) {
            int b  = m / NQTOK;
            int qq = m - b * NQTOK;
            int qi = qq / 7;
            int qj = qq - qi * 7;
            asrc[j] = b * NTOK + qi * 2 * RESOL + qj * 2;
        } else {
            asrc[j] = m;
        }
    }
    const int bsrc = bn + (lrow & 63);   // B: 64 rows x 4 chunks = 256 -> 1/thread

    const uint32_t sbase = (uint32_t)__cvta_generic_to_shared(gsm);

    auto issue = [&](int it, int s) {
        const int k0 = it * 32;          // in halfs
        uint32_t abase = sbase + (uint32_t)(s * HSTAGE_W) * 4u;
#pragma unroll
        for (int j = 0; j < 2; j++) {
            uint32_t dst = abase + (uint32_t)((lrow + 64 * j) * HLD + seg * 4) * 4u;
            cp_async16(dst, A + (size_t)asrc[j] * INDIM + k0 + seg * 8);
        }
        if (lrow < 64) {
            uint32_t bbase = abase + (uint32_t)HA_STAGE * 4u;
            uint32_t dst = bbase + (uint32_t)(lrow * HLD + seg * 4) * 4u;
            cp_async16(dst, W + (size_t)bsrc * INDIM + k0 + seg * 8);
        }
        cp_commit();
    };

    float acc[2][4][4] = {};

    issue(0, 0);
    issue(1, 1);

    const int NIT = INDIM / 32;   // 12
    for (int it = 0; it < NIT; it++) {
        if (it < NIT - 1) asm volatile("cp.async.wait_group 1;\n" ::: "memory");
        else              asm volatile("cp.async.wait_group 0;\n" ::: "memory");
        __syncthreads();
        if (it + 2 < NIT) issue(it + 2, (it + 2) % 3);

        const uint32_t* As = gsm + (it % 3) * HSTAGE_W;
        const uint32_t* Bs = As + HA_STAGE;

        // 2 k-slices of k=16 (8 u32 each)
#pragma unroll
        for (int kc = 0; kc < 2; kc++) {
            const int kb = kc * 8;
            uint32_t af[2][4];
#pragma unroll
            for (int mi = 0; mi < 2; mi++) {
                int m0 = wm + mi * 16 + g8;
                af[mi][0] = As[m0 * HLD + kb + tg];
                af[mi][1] = As[(m0 + 8) * HLD + kb + tg];
                af[mi][2] = As[m0 * HLD + kb + tg + 4];
                af[mi][3] = As[(m0 + 8) * HLD + kb + tg + 4];
            }
            uint32_t bf[4][2];
#pragma unroll
            for (int ni = 0; ni < 4; ni++) {
                int n0 = wn + ni * 8 + g8;
                bf[ni][0] = Bs[n0 * HLD + kb + tg];
                bf[ni][1] = Bs[n0 * HLD + kb + tg + 4];
            }
#pragma unroll
            for (int mi = 0; mi < 2; mi++)
#pragma unroll
                for (int ni = 0; ni < 4; ni++)
                    mma_f16(acc[mi][ni], af[mi], bf[ni]);
        }
    }

    // BN epilogue (C frag layout: c0,c1 row g8 cols 2tg,2tg+1; c2,c3 row g8+8)
#pragma unroll
    for (int ni = 0; ni < 4; ni++) {
        int n0 = bn + wn + ni * 8 + 2 * tg;
        float sc0 = bn_g[n0] * rsqrtf(bn_v[n0] + BN_EPS);
        float bi0 = bn_b[n0] - bn_m[n0] * sc0;
        float sc1 = bn_g[n0 + 1] * rsqrtf(bn_v[n0 + 1] + BN_EPS);
        float bi1 = bn_b[n0 + 1] - bn_m[n0 + 1] * sc1;
#pragma unroll
        for (int mi = 0; mi < 2; mi++) {
#pragma unroll
            for (int rr = 0; rr < 2; rr++) {
                int mrow = bm + wm + mi * 16 + g8 + rr * 8;
                float2 val;
                val.x = fmaf(acc[mi][ni][rr * 2 + 0], sc0, bi0);
                val.y = fmaf(acc[mi][ni][rr * 2 + 1], sc1, bi1);
                *(float2*)(C + (size_t)mrow * N + n0) = val;
            }
        }
    }
}

// ---------------------------------------------------------------------------
// Precompute bias table
// ---------------------------------------------------------------------------
__global__ __launch_bounds__(256)
void bias_pre_kernel(const float* __restrict__ biases, const int* __restrict__ idxs,
                     float* __restrict__ tab)
{
    int i = blockIdx.x * 256 + threadIdx.x;
    if (i < NQTOK * NTOK) {
        int id = idxs[i];
#pragma unroll
        for (int h = 0; h < HEADS; h++)
            tab[(size_t)h * (NQTOK * NTOK) + i] = biases[h * NTOK + id];
    }
}

// ---------------------------------------------------------------------------
// Tensor-core attention (mma.sync tf32), 2 blocks per (b,h), 32 q rows each.
// Identical to R5 except the final store emits fp16 (half2) for GEMM3.
// ---------------------------------------------------------------------------
#define LDQ 17
#define LDK 17
#define LDV 201
#define LDS_ 201
#define QROWS 32
#define QS_OFF 0
#define KS_OFF (QS_OFF + QROWS*LDQ)
#define VT_OFF (KS_OFF + 200*LDK)
#define SB_OFF (VT_OFF + 32*LDV)
#define ATTN_SMEM_U32 (SB_OFF + QROWS*LDS_)
#define ATTN_SMEM_BYTES (ATTN_SMEM_U32 * 4)

__global__ __launch_bounds__(256)
void attn_tc_kernel(const float* __restrict__ kv, const float* __restrict__ qg,
                    const float* __restrict__ btab, __half* __restrict__ ao)
{
    extern __shared__ uint32_t sm[];
    uint32_t* Qs = sm + QS_OFF;
    uint32_t* Ks = sm + KS_OFF;
    uint32_t* Vt = sm + VT_OFF;
    uint32_t* Sb = sm + SB_OFF;

    const int tid   = threadIdx.x;
    const int half_ = blockIdx.x & 1;
    const int bh    = blockIdx.x >> 1;
    const int b     = bh / HEADS;
    const int h     = bh - b * HEADS;
    const int qbase = half_ * QROWS;
    const int w     = tid >> 5;
    const int lane  = tid & 31;
    const int g8    = lane >> 2;
    const int tg    = lane & 3;
    const float* bt = btab + (size_t)h * (NQTOK * NTOK);

    for (int i = tid; i < QROWS * LDQ; i += 256) Qs[i] = 0;
    for (int i = tid; i < 200 * LDK; i += 256) Ks[i] = 0;
    for (int i = tid; i < 32 * 5; i += 256) {
        int d = i / 5, n = 196 + (i % 5);
        Vt[d * LDV + n] = 0;
    }
    __syncthreads();

    for (int i = tid; i < QROWS * KD; i += 256) {
        int qi = i >> 4, d = i & 15;
        if (qbase + qi < NQTOK)
            Qs[qi * LDQ + d] =
                f2tf32(qg[(size_t)(b * NQTOK + qbase + qi) * KEYATTN + h * KD + d]);
    }
    for (int i = tid; i < NTOK * KD; i += 256) {
        int n = i >> 4, d = i & 15;
        Ks[n * LDK + d] = f2tf32(kv[(size_t)(b * NTOK + n) * KVD + h * (KD + VD) + d]);
    }
    for (int i = tid; i < NTOK * VD; i += 256) {
        int n = i >> 5, d = i & 31;
        Vt[d * LDV + n] = f2tf32(kv[(size_t)(b * NTOK + n) * KVD + h * (KD + VD) + KD + d]);
    }
    __syncthreads();

    {
        const int mt = w >> 2;
        const int nq = w & 3;
        const int nt0 = (nq == 0) ? 0 : (nq == 1) ? 6 : (nq == 2) ? 12 : 18;
        const int nt1 = (nq == 0) ? 6 : (nq == 1) ? 12 : (nq == 2) ? 18 : 25;

        uint32_t a[2][4];
#pragma unroll
        for (int ks = 0; ks < 2; ks++) {
            int k0 = ks * 8;
            int r = mt * 16 + g8;
            a[ks][0] = Qs[r * LDQ + k0 + tg];
            a[ks][1] = Qs[(r + 8) * LDQ + k0 + tg];
            a[ks][2] = Qs[r * LDQ + k0 + tg + 4];
            a[ks][3] = Qs[(r + 8) * LDQ + k0 + tg + 4];
        }
        for (int nt = nt0; nt < nt1; nt++) {
            float c[4] = {0.f, 0.f, 0.f, 0.f};
#pragma unroll
            for (int ks = 0; ks < 2; ks++) {
                int k0 = ks * 8;
                uint32_t bfr[2];
                bfr[0] = Ks[(nt * 8 + g8) * LDK + k0 + tg];
                bfr[1] = Ks[(nt * 8 + g8) * LDK + k0 + tg + 4];
                mma_tf32(c, a[ks], bfr);
            }
            int r0 = mt * 16 + g8;
            int r1 = r0 + 8;
            int gq0 = qbase + r0;
            int gq1 = qbase + r1;
            int col = nt * 8 + 2 * tg;
            float2 bv0 = make_float2(0.f, 0.f), bv1 = make_float2(0.f, 0.f);
            if (col < NTOK) {
                if (gq0 < NQTOK) bv0 = *(const float2*)(bt + gq0 * NTOK + col);
                if (gq1 < NQTOK) bv1 = *(const float2*)(bt + gq1 * NTOK + col);
            }
            Sb[r0 * LDS_ + col]     = __float_as_uint(fmaf(c[0], ATTNSCALE, bv0.x));
            Sb[r0 * LDS_ + col + 1] = __float_as_uint(fmaf(c[1], ATTNSCALE, bv0.y));
            Sb[r1 * LDS_ + col]     = __float_as_uint(fmaf(c[2], ATTNSCALE, bv1.x));
            Sb[r1 * LDS_ + col + 1] = __float_as_uint(fmaf(c[3], ATTNSCALE, bv1.y));
        }
    }
    __syncthreads();

    for (int r = w; r < QROWS; r += 8) {
        float s[7];
        float mx = -1e30f;
#pragma unroll
        for (int it = 0; it < 7; it++) {
            int n = lane + it * 32;
            float v = (n < NTOK) ? __uint_as_float(Sb[r * LDS_ + n]) : -1e30f;
            s[it] = v;
            mx = fmaxf(mx, v);
        }
#pragma unroll
        for (int o = 16; o > 0; o >>= 1)
            mx = fmaxf(mx, __shfl_xor_sync(0xffffffffu, mx, o));
        float sum = 0.f;
        float e[7];
#pragma unroll
        for (int it = 0; it < 7; it++) {
            int n = lane + it * 32;
            float ev = (n < NTOK) ? __expf(s[it] - mx) : 0.f;
            e[it] = ev;
            sum += ev;
        }
#pragma unroll
        for (int o = 16; o > 0; o >>= 1)
            sum += __shfl_xor_sync(0xffffffffu, sum, o);
        float inv = 1.f / sum;
#pragma unroll
        for (int it = 0; it < 7; it++) {
            int n = lane + it * 32;
            if (n < NTOK)      Sb[r * LDS_ + n] = f2tf32(e[it] * inv);
            else if (n < 200)  Sb[r * LDS_ + n] = 0;
        }
    }
    __syncthreads();

    {
        const int mt = w >> 2;
        const int dh = w & 3;
        float acc[4] = {0.f, 0.f, 0.f, 0.f};
        for (int ks = 0; ks < 25; ks++) {
            int k0 = ks * 8;
            uint32_t a[4];
            int r = mt * 16 + g8;
            a[0] = Sb[r * LDS_ + k0 + tg];
            a[1] = Sb[(r + 8) * LDS_ + k0 + tg];
            a[2] = Sb[r * LDS_ + k0 + tg + 4];
            a[3] = Sb[(r + 8) * LDS_ + k0 + tg + 4];
            uint32_t bfr[2];
            bfr[0] = Vt[(dh * 8 + g8) * LDV + k0 + tg];
            bfr[1] = Vt[(dh * 8 + g8) * LDV + k0 + tg + 4];
            mma_tf32(acc, a, bfr);
        }
        int d0  = dh * 8 + 2 * tg;
        int gq0 = qbase + mt * 16 + g8;
        int gq1 = gq0 + 8;
        if (gq0 < NQTOK) {
            float o0 = acc[0], o1 = acc[1];
            __half2 v = __floats2half2_rn(o0 / (1.f + __expf(-o0)),
                                          o1 / (1.f + __expf(-o1)));
            *(uint32_t*)(ao + (size_t)(b * NQTOK + gq0) * VALATTN + h * VD + d0) =
                *(uint32_t*)&v;
        }
        if (gq1 < NQTOK) {
            float o0 = acc[2], o1 = acc[3];
            __half2 v = __floats2half2_rn(o0 / (1.f + __expf(-o0)),
                                          o1 / (1.f + __expf(-o1)));
            *(uint32_t*)(ao + (size_t)(b * NQTOK + gq1) * VALATTN + h * VD + d0) =
                *(uint32_t*)&v;
        }
    }
}

// ---------------------------------------------------------------------------
// Launch
// ---------------------------------------------------------------------------
extern "C" void kernel_launch(void* const* d_in, const int* in_sizes, int n_in,
                              void* d_out, int out_size)
{
    const float* x     = (const float*)d_in[0];
    const float* kv_w  = (const float*)d_in[1];
    const float* kv_g  = (const float*)d_in[2];
    const float* kv_b  = (const float*)d_in[3];
    const float* kv_m  = (const float*)d_in[4];
    const float* kv_v  = (const float*)d_in[5];
    const float* q_w   = (const float*)d_in[6];
    const float* q_g   = (const float*)d_in[7];
    const float* q_b   = (const float*)d_in[8];
    const float* q_m   = (const float*)d_in[9];
    const float* q_v   = (const float*)d_in[10];
    const float* pj_w  = (const float*)d_in[11];
    const float* pj_g  = (const float*)d_in[12];
    const float* pj_b  = (const float*)d_in[13];
    const float* pj_m  = (const float*)d_in[14];
    const float* pj_v  = (const float*)d_in[15];
    const float* biases    = (const float*)d_in[16];
    const int*   bias_idxs = (const int*)d_in[17];
    float* out = (float*)d_out;

    float  *kv_buf, *q_buf, *btab;
    __half *aoh, *xh, *wh;
    cudaGetSymbolAddress((void**)&kv_buf, g_kv);
    cudaGetSymbolAddress((void**)&q_buf,  g_q);
    cudaGetSymbolAddress((void**)&aoh,    g_aoh);
    cudaGetSymbolAddress((void**)&btab,   g_btab);
    cudaGetSymbolAddress((void**)&xh,     g_xh);
    cudaGetSymbolAddress((void**)&wh,     g_wh);

    cudaFuncSetAttribute(attn_tc_kernel,
                         cudaFuncAttributeMaxDynamicSharedMemorySize, ATTN_SMEM_BYTES);
    cudaFuncSetAttribute(gemm_h_bn<false>,
                         cudaFuncAttributeMaxDynamicSharedMemorySize, GEMM_SMEM_BYTES);
    cudaFuncSetAttribute(gemm_h_bn<true>,
                         cudaFuncAttributeMaxDynamicSharedMemorySize, GEMM_SMEM_BYTES);

    // Convert x and weights to fp16
    {
        int n4 = (M1 * INDIM) / 4;
        f32_to_f16_kernel<<<(n4 + 255) / 256, 256>>>((const float4*)x, (uint2*)xh, n4);
        int nkv = (KVD * INDIM) / 4;
        f32_to_f16_kernel<<<(nkv + 255) / 256, 256>>>((const float4*)kv_w, (uint2*)(wh + WR_KV), nkv);
        int nq = (KEYATTN * INDIM) / 4;
        f32_to_f16_kernel<<<(nq + 255) / 256, 256>>>((const float4*)q_w, (uint2*)(wh + WR_Q), nq);
        int npj = (OUTDIM * INDIM) / 4;
        f32_to_f16_kernel<<<(npj + 255) / 256, 256>>>((const float4*)pj_w, (uint2*)(wh + WR_PJ), npj);
    }

    bias_pre_kernel<<<(NQTOK * NTOK + 255) / 256, 256>>>(biases, bias_idxs, btab);

    // GEMM1: kv = BN(x @ kv_w^T)   [50176 x 576]
    gemm_h_bn<false><<<dim3(KVD / 64, M1 / 128), 256, GEMM_SMEM_BYTES>>>(
        xh, wh + WR_KV, kv_g, kv_b, kv_m, kv_v, kv_buf, KVD);

    // GEMM2: q = BN(xq @ q_w^T)    [12544 x 192], gathered rows
    gemm_h_bn<true><<<dim3(KEYATTN / 64, M2 / 128), 256, GEMM_SMEM_BYTES>>>(
        xh, wh + WR_Q, q_g, q_b, q_m, q_v, q_buf, KEYATTN);

    // Attention (split: 2 blocks per (b,h)), writes fp16
    attn_tc_kernel<<<BATCH * HEADS * 2, 256, ATTN_SMEM_BYTES>>>(
        kv_buf, q_buf, btab, aoh);

    // GEMM3: out = BN(silu_attn @ pj_w^T)  [12544 x 512]
    gemm_h_bn<false><<<dim3(OUTDIM / 64, M2 / 128), 256, GEMM_SMEM_BYTES>>>(
        aoh, wh + WR_PJ, pj_g, pj_b, pj_m, pj_v, out, OUTDIM);
}